// round 13
// baseline (speedup 1.0000x reference)
#include <cuda_runtime.h>
#include <cstdint>
#include <math.h>

// Problem constants
static constexpr int Bc = 2, Sc = 2048, Hc = 2048, NHc = 16, HDc = 128, BSZ = 256;
static constexpr int Mc = Bc * Sc;  // 4096
static constexpr float SCALE = 0.08838834764831845f;  // 1/sqrt(128)

// Scratch (device globals — no allocation allowed)
__device__ float g_q[Bc * Sc * Hc];
__device__ float g_k[Bc * Sc * Hc];
__device__ float g_vt[Bc * Sc * Hc];      // V transposed: [b, h, d, s]
__device__ float g_ao[Bc * Sc * Hc];
__device__ float g_hsr[Bc * Sc * Hc];     // tf32-rounded hidden_states
__device__ float g_wr[4][Hc * Hc];        // tf32-rounded Wq,Wk,Wv,Wo (contiguous)

// ---------------------------------------------------------------------------
// helpers
// ---------------------------------------------------------------------------
__device__ __forceinline__ uint32_t smem_u32(const void* p) {
    uint32_t a;
    asm("{ .reg .u64 t; cvta.to.shared.u64 t, %1; cvt.u32.u64 %0, t; }"
        : "=r"(a) : "l"(p));
    return a;
}
__device__ __forceinline__ uint32_t f2tf32(float x) {
    uint32_t r;
    asm("cvt.rna.tf32.f32 %0, %1;" : "=r"(r) : "f"(x));
    return r;
}
__device__ __forceinline__ float rnd_tf32(float x) {
    return __uint_as_float(f2tf32(x));
}
__device__ __forceinline__ void ldsm_x4(uint32_t* r, uint32_t addr) {
    asm volatile("ldmatrix.sync.aligned.m8n8.x4.shared.b16 {%0,%1,%2,%3}, [%4];"
                 : "=r"(r[0]), "=r"(r[1]), "=r"(r[2]), "=r"(r[3]) : "r"(addr));
}
__device__ __forceinline__ void mma_tf32(float* d, const uint32_t* a,
                                         uint32_t b0, uint32_t b1) {
    asm volatile(
        "mma.sync.aligned.m16n8k8.row.col.f32.tf32.tf32.f32 "
        "{%0,%1,%2,%3}, {%4,%5,%6,%7}, {%8,%9}, {%0,%1,%2,%3};"
        : "+f"(d[0]), "+f"(d[1]), "+f"(d[2]), "+f"(d[3])
        : "r"(a[0]), "r"(a[1]), "r"(a[2]), "r"(a[3]), "r"(b0), "r"(b1));
}
__device__ __forceinline__ void cpa16(uint32_t dst, const void* src) {
    asm volatile("cp.async.cg.shared.global [%0], [%1], 16;"
                 :: "r"(dst), "l"(src) : "memory");
}
__device__ __forceinline__ void cpa_commit() {
    asm volatile("cp.async.commit_group;" ::: "memory");
}
__device__ __forceinline__ void cpa_wait1() {
    asm volatile("cp.async.wait_group 1;" ::: "memory");
}
__device__ __forceinline__ void cpa_wait0() {
    asm volatile("cp.async.wait_group 0;" ::: "memory");
}

// ---------------------------------------------------------------------------
// tf32 pre-rounding, all 5 tensors in one launch.
// ---------------------------------------------------------------------------
__global__ __launch_bounds__(256) void round_all(const float* __restrict__ hs,
                                                 const float* __restrict__ Wq,
                                                 const float* __restrict__ Wk,
                                                 const float* __restrict__ Wv,
                                                 const float* __restrict__ Wo,
                                                 float* __restrict__ hsr,
                                                 float* __restrict__ wr) {
    const int nHS4 = Bc * Sc * Hc / 4;   // 2M
    const int nW4 = Hc * Hc / 4;         // 1M
    int i = blockIdx.x * blockDim.x + threadIdx.x;
    const float4* src;
    float4* dst;
    int idx;
    if (i < nHS4) {
        src = (const float4*)hs; dst = (float4*)hsr; idx = i;
    } else {
        int j = i - nHS4;
        int w = j / nW4;
        idx = j - w * nW4;
        src = (const float4*)(w == 0 ? Wq : w == 1 ? Wk : w == 2 ? Wv : Wo);
        dst = (float4*)wr + (size_t)w * nW4;
    }
    float4 v = src[idx];
    float4 r;
    r.x = rnd_tf32(v.x); r.y = rnd_tf32(v.y);
    r.z = rnd_tf32(v.z); r.w = rnd_tf32(v.w);
    dst[idx] = r;
}

// ---------------------------------------------------------------------------
// GEMM machinery: CTA tile 256(M) x 128(N), BK=32, 512 threads (16 warps,
// 4m x 4n grid, warp tile 64x32 -- identical per-warp code/accum order as
// the validated 128x128 version). 3-stage cp.async, 1 CTA/SM.
// ---------------------------------------------------------------------------
static constexpr int RSF = 36;
static constexpr int ATILE_A = 256 * RSF * 4;      // 36864 bytes
static constexpr int ATILE_B = 128 * RSF * 4;      // 18432 bytes
static constexpr int STAGE = ATILE_A + ATILE_B;    // 55296 bytes
static constexpr int GEMM_SMEM = 3 * STAGE;        // 165888 bytes
static constexpr int KD = 2048;
static constexpr int NKBg = KD / 32;               // 64

struct GemmCore {
    uint32_t sb;
    const float* gA0;
    const float* gB0;
    uint32_t so0;
    uint32_t aFragOff, bFragOff;
    float acc[4][4][4];

    __device__ __forceinline__ void init(uint32_t sb_, const float* A, const float* W,
                                         int m0, int n0, int tid) {
        sb = sb_;
        const int lane = tid & 31, wid = tid >> 5;
        const int wm = wid >> 2, wn = wid & 3;       // 4 x 4 warp grid
        const int row = tid >> 3, ch = tid & 7;      // row 0..63
        gA0 = A + (size_t)(m0 + row) * KD + ch * 4;
        gB0 = W + (size_t)(n0 + row) * KD + ch * 4;
        so0 = row * (RSF * 4) + ch * 16;
        const int arow = wm * 64 + (lane & 7) + ((lane >> 3) & 1) * 8;
        aFragOff = arow * (RSF * 4) + ((lane >> 4) & 1) * 16;
        const int brow = wn * 32 + (lane & 7) + ((lane >> 4) & 1) * 8;
        bFragOff = brow * (RSF * 4) + ((lane >> 3) & 1) * 16;
#pragma unroll
        for (int t = 0; t < 4; ++t)
#pragma unroll
            for (int u = 0; u < 4; ++u)
#pragma unroll
                for (int e = 0; e < 4; ++e) acc[t][u][e] = 0.f;
    }

    __device__ __forceinline__ void ld_stage(uint32_t st, int kb) {
        // A: 256 rows, 4 slices of 64 rows per thread
#pragma unroll
        for (int i = 0; i < 4; ++i)
            cpa16(st + so0 + i * (64 * RSF * 4), gA0 + kb * 32 + i * (64 * KD));
        // B: 128 rows, 2 slices
#pragma unroll
        for (int i = 0; i < 2; ++i)
            cpa16(st + ATILE_A + so0 + i * (64 * RSF * 4), gB0 + kb * 32 + i * (64 * KD));
        cpa_commit();
    }

    __device__ __forceinline__ void run() {
        ld_stage(sb, 0);
        ld_stage(sb + STAGE, 1);
        int stage = 0;
        for (int kb = 0; kb < NKBg; ++kb) {
            cpa_wait1();
            __syncthreads();
            {
                int ns = stage + 2;
                if (ns >= 3) ns -= 3;
                if (kb + 2 < NKBg) {
                    ld_stage(sb + ns * STAGE, kb + 2);
                } else {
                    cpa_commit();
                }
            }
            const uint32_t sA = sb + stage * STAGE;
            const uint32_t sB = sA + ATILE_A;
#pragma unroll
            for (int ks = 0; ks < 4; ++ks) {
                uint32_t af[4][4];
#pragma unroll
                for (int t = 0; t < 4; ++t)
                    ldsm_x4(af[t], sA + aFragOff + t * (16 * RSF * 4) + ks * 32);
                uint32_t bf[2][4];
#pragma unroll
                for (int p = 0; p < 2; ++p)
                    ldsm_x4(bf[p], sB + bFragOff + p * (16 * RSF * 4) + ks * 32);
#pragma unroll
                for (int t = 0; t < 4; ++t) {
                    mma_tf32(acc[t][0], af[t], bf[0][0], bf[0][1]);
                    mma_tf32(acc[t][1], af[t], bf[0][2], bf[0][3]);
                    mma_tf32(acc[t][2], af[t], bf[1][0], bf[1][1]);
                    mma_tf32(acc[t][3], af[t], bf[1][2], bf[1][3]);
                }
            }
            if (++stage == 3) stage = 0;
        }
    }
};

// Merged Q/K/V projection GEMM, half of heads per launch.
// grid (24, 16): bx>>3 = widx (0=Q,1=K,2=V), (bx&7)+ntOff = head; by = m-tile(256).
__global__ __launch_bounds__(512, 1) void gemm_qkv(const float* __restrict__ A,
                                                   const float* __restrict__ Wbase,
                                                   float* __restrict__ Qo,
                                                   float* __restrict__ Ko,
                                                   float* __restrict__ Vto,
                                                   int ntOff) {
    extern __shared__ __align__(128) char smem[];
    const int tid = threadIdx.x;
    const int widx = blockIdx.x >> 3;
    const int n0 = ((blockIdx.x & 7) + ntOff) * 128;
    const int m0 = blockIdx.y * 256;
    const float* W = Wbase + (size_t)widx * Hc * Hc;

    GemmCore gc;
    gc.init(smem_u32(smem), A, W, m0, n0, tid);
    gc.run();

    const int lane = tid & 31, wid = tid >> 5;
    const int wm = wid >> 2, wn = wid & 3;
    const int crow = lane >> 2, ccol = (lane & 3) * 2;
    if (widx == 2) {
        // V: write transposed per head [b,h,d,s], tf32-rounded
#pragma unroll
        for (int t = 0; t < 4; ++t) {
            int r0 = m0 + wm * 64 + t * 16 + crow;
#pragma unroll
            for (int u = 0; u < 4; ++u) {
                int c = n0 + wn * 32 + u * 8 + ccol;
#pragma unroll
                for (int e = 0; e < 4; ++e) {
                    int r = r0 + (e >> 1) * 8;
                    int cc = c + (e & 1);
                    int bq = r >> 11, s = r & 2047;
                    int hh = cc >> 7, d = cc & 127;
                    Vto[(((size_t)bq * NHc + hh) * HDc + d) * Sc + s] =
                        rnd_tf32(gc.acc[t][u][e]);
                }
            }
        }
    } else {
        float* C = (widx == 0) ? Qo : Ko;
#pragma unroll
        for (int t = 0; t < 4; ++t) {
            int r0 = m0 + wm * 64 + t * 16 + crow;
#pragma unroll
            for (int u = 0; u < 4; ++u) {
                int c = n0 + wn * 32 + u * 8 + ccol;
                *(float2*)(C + (size_t)r0 * Hc + c) =
                    make_float2(rnd_tf32(gc.acc[t][u][0]), rnd_tf32(gc.acc[t][u][1]));
                *(float2*)(C + (size_t)(r0 + 8) * Hc + c) =
                    make_float2(rnd_tf32(gc.acc[t][u][2]), rnd_tf32(gc.acc[t][u][3]));
            }
        }
    }
}

// Output projection GEMM (plain fp32 epilogue). grid (16, 16).
__global__ __launch_bounds__(512, 1) void gemm_wo(const float* __restrict__ A,
                                                  const float* __restrict__ W,
                                                  float* __restrict__ C) {
    extern __shared__ __align__(128) char smem[];
    const int tid = threadIdx.x;
    const int n0 = blockIdx.x * 128;
    const int m0 = blockIdx.y * 256;

    GemmCore gc;
    gc.init(smem_u32(smem), A, W, m0, n0, tid);
    gc.run();

    const int lane = tid & 31, wid = tid >> 5;
    const int wm = wid >> 2, wn = wid & 3;
    const int crow = lane >> 2, ccol = (lane & 3) * 2;
#pragma unroll
    for (int t = 0; t < 4; ++t) {
        int r0 = m0 + wm * 64 + t * 16 + crow;
#pragma unroll
        for (int u = 0; u < 4; ++u) {
            int c = n0 + wn * 32 + u * 8 + ccol;
            *(float2*)(C + (size_t)r0 * Hc + c) =
                make_float2(gc.acc[t][u][0], gc.acc[t][u][1]);
            *(float2*)(C + (size_t)(r0 + 8) * Hc + c) =
                make_float2(gc.acc[t][u][2], gc.acc[t][u][3]);
        }
    }
}

// ---------------------------------------------------------------------------
// Tensor-core block-softmax attention, 2-CTA/SM, head-half per launch.
// (unchanged from R10; bit-identical numerics)
// ---------------------------------------------------------------------------
static constexpr int AQ = 0;
static constexpr int AB = 8448;
static constexpr int APc = 17152;
static constexpr int ARED = 21504;
static constexpr int ATTN_SMEM = 21760 * 4;  // 87040 bytes

__global__ __launch_bounds__(256, 2) void attn_mma(const float* __restrict__ Q,
                                                   const float* __restrict__ K,
                                                   const float* __restrict__ Vt,
                                                   float* __restrict__ O,
                                                   int hOff) {
    extern __shared__ __align__(1024) float sma[];
    const uint32_t sb = smem_u32(sma);
    const int tid = threadIdx.x, lane = tid & 31, wid = tid >> 5;
    const int ms = wid >> 1, nh = wid & 1, g = lane >> 2, tig = lane & 3;
    const int qt = 31 - blockIdx.x;  // heavy tiles first
    const int h = blockIdx.y + hOff, b = blockIdx.z;
    const int q0 = qt * 64, bi = qt >> 2, sp = qt & 3;
    const size_t base = (size_t)b * Sc * Hc + (size_t)h * HDc;
    const float* Kb = K + base;
    const float* Qb = Q + base;
    const float* Vtb = Vt + ((size_t)(b * NHc + h) * HDc) * Sc;

    const int rowK = tid >> 5, colK = (tid & 31) * 4;          // K: 64r x 128d
    const int rowV = tid >> 4, colV = (tid & 15) * 4;          // V: 128d x 64k
    const uint32_t kDst = sb + (AB + rowK * 132 + colK) * 4;
    const uint32_t vDst = sb + (AB + rowV * 68 + colV) * 4;

    // prologue: Q tile + K block0 chunk0
#pragma unroll
    for (int i = 0; i < 8; ++i)
        cpa16(sb + (AQ + (rowK + 8 * i) * 132 + colK) * 4,
              Qb + (size_t)(q0 + rowK + 8 * i) * Hc + colK);
#pragma unroll
    for (int i = 0; i < 8; ++i)
        cpa16(kDst + i * (8 * 132 * 4), Kb + (size_t)(rowK + 8 * i) * Hc + colK);
    cpa_commit();

    const int frow = (lane & 7) + ((lane >> 3) & 1) * 8;
    const uint32_t aQ = sb + ((AQ + (ms * 16 + frow) * 132 + ((lane >> 4) & 1) * 4) * 4);
    const int browk = (lane & 7) + ((lane >> 4) & 1) * 8;
    const uint32_t bcolk = ((lane >> 3) & 1) * 4;
    const uint32_t bK0 = sb + AB * 4 + ((nh * 32 + browk) * 132 + bcolk) * 4;
    const uint32_t bK1 = bK0 + 16 * 132 * 4;
    const uint32_t aPc = sb + ((APc + (ms * 16 + frow) * 68 + ((lane >> 4) & 1) * 4) * 4);
    uint32_t bV[4];
#pragma unroll
    for (int p = 0; p < 4; ++p)
        bV[p] = sb + AB * 4 + ((nh * 64 + p * 16 + browk) * 68 + bcolk) * 4;

    float o[8][4];
#pragma unroll
    for (int u = 0; u < 8; ++u)
#pragma unroll
        for (int e = 0; e < 4; ++e) o[u][e] = 0.f;

    const int row0 = ms * 16 + g;
    const int qi0 = q0 + row0, qi1 = qi0 + 8;

    for (int j = 0; j <= bi; ++j) {
        const int nc = (j < bi) ? 4 : (sp + 1);
        const int kb = j * BSZ;
        float s[16][4];
#pragma unroll
        for (int t = 0; t < 16; ++t)
#pragma unroll
            for (int e = 0; e < 4; ++e) s[t][e] = 0.f;

        // ---- QK chunks ----
        for (int c = 0; c < nc; ++c) {
            cpa_wait0();
            __syncthreads();
#pragma unroll
            for (int ks = 0; ks < 16; ++ks) {
                uint32_t af[4];
                ldsm_x4(af, aQ + ks * 32);
                uint32_t bf[4];
                ldsm_x4(bf, bK0 + ks * 32);
                mma_tf32(s[c * 4 + 0], af, bf[0], bf[1]);
                mma_tf32(s[c * 4 + 1], af, bf[2], bf[3]);
                ldsm_x4(bf, bK1 + ks * 32);
                mma_tf32(s[c * 4 + 2], af, bf[0], bf[1]);
                mma_tf32(s[c * 4 + 3], af, bf[2], bf[3]);
            }
            __syncthreads();
            if (c + 1 < nc) {
                const int ka = kb + (c + 1) * 64;
#pragma unroll
                for (int i = 0; i < 8; ++i)
                    cpa16(kDst + i * (8 * 132 * 4),
                          Kb + (size_t)(ka + rowK + 8 * i) * Hc + colK);
            } else {
#pragma unroll
                for (int i = 0; i < 8; ++i)
                    cpa16(vDst + i * (16 * 68 * 4),
                          Vtb + (size_t)(rowV + 16 * i) * Sc + kb + colV);
            }
            cpa_commit();
        }

        // ---- per-block softmax ----
        const bool diag = (j == bi);
        const int ntile = nc * 4;
        float mx0 = -1e30f, mx1 = -1e30f;
        for (int t = 0; t < ntile; ++t) {
            if (diag) {
                int col = kb + 64 * (t >> 2) + nh * 32 + 8 * (t & 3) + 2 * tig;
                if (col > qi0) s[t][0] = -1e30f;
                if (col + 1 > qi0) s[t][1] = -1e30f;
                if (col > qi1) s[t][2] = -1e30f;
                if (col + 1 > qi1) s[t][3] = -1e30f;
            }
            mx0 = fmaxf(mx0, fmaxf(s[t][0], s[t][1]));
            mx1 = fmaxf(mx1, fmaxf(s[t][2], s[t][3]));
        }
        mx0 = fmaxf(mx0, __shfl_xor_sync(0xffffffffu, mx0, 1));
        mx0 = fmaxf(mx0, __shfl_xor_sync(0xffffffffu, mx0, 2));
        mx1 = fmaxf(mx1, __shfl_xor_sync(0xffffffffu, mx1, 1));
        mx1 = fmaxf(mx1, __shfl_xor_sync(0xffffffffu, mx1, 2));
        float l0 = 0.f, l1 = 0.f;
        for (int t = 0; t < ntile; ++t) {
            float p0 = (s[t][0] <= -1e29f) ? 0.f : __expf(SCALE * (s[t][0] - mx0));
            float p1 = (s[t][1] <= -1e29f) ? 0.f : __expf(SCALE * (s[t][1] - mx0));
            float p2 = (s[t][2] <= -1e29f) ? 0.f : __expf(SCALE * (s[t][2] - mx1));
            float p3 = (s[t][3] <= -1e29f) ? 0.f : __expf(SCALE * (s[t][3] - mx1));
            s[t][0] = p0; s[t][1] = p1; s[t][2] = p2; s[t][3] = p3;
            l0 += p0 + p1;
            l1 += p2 + p3;
        }
        l0 += __shfl_xor_sync(0xffffffffu, l0, 1);
        l0 += __shfl_xor_sync(0xffffffffu, l0, 2);
        l1 += __shfl_xor_sync(0xffffffffu, l1, 1);
        l1 += __shfl_xor_sync(0xffffffffu, l1, 2);
        if (tig == 0) {
            sma[ARED + row0 * 2 + nh] = mx0;
            sma[ARED + 128 + row0 * 2 + nh] = l0;
            sma[ARED + (row0 + 8) * 2 + nh] = mx1;
            sma[ARED + 128 + (row0 + 8) * 2 + nh] = l1;
        }
        __syncthreads();
        float f0, f1;
        {
            float mo0 = sma[ARED + row0 * 2 + (nh ^ 1)];
            float lo0 = sma[ARED + 128 + row0 * 2 + (nh ^ 1)];
            float mo1 = sma[ARED + (row0 + 8) * 2 + (nh ^ 1)];
            float lo1 = sma[ARED + 128 + (row0 + 8) * 2 + (nh ^ 1)];
            float M0 = fmaxf(mx0, mo0), M1 = fmaxf(mx1, mo1);
            float cc0 = __expf(SCALE * (mx0 - M0)), co0 = __expf(SCALE * (mo0 - M0));
            float cc1 = __expf(SCALE * (mx1 - M1)), co1 = __expf(SCALE * (mo1 - M1));
            f0 = cc0 / (l0 * cc0 + lo0 * co0 + 1e-30f);
            f1 = cc1 / (l1 * cc1 + lo1 * co1 + 1e-30f);
        }

        // ---- PV chunks ----
        for (int c = 0; c < nc; ++c) {
#pragma unroll
            for (int tt = 0; tt < 4; ++tt) {
                int t = c * 4 + tt;
                int col = nh * 32 + 8 * tt + 2 * tig;
                uint32_t a0 = sb + (APc + (ms * 16 + g) * 68 + col) * 4;
                asm volatile("st.shared.v2.b32 [%0], {%1,%2};"
                             :: "r"(a0), "r"(f2tf32(s[t][0] * f0)),
                                "r"(f2tf32(s[t][1] * f0)) : "memory");
                asm volatile("st.shared.v2.b32 [%0], {%1,%2};"
                             :: "r"(a0 + 8 * 68 * 4), "r"(f2tf32(s[t][2] * f1)),
                                "r"(f2tf32(s[t][3] * f1)) : "memory");
            }
            cpa_wait0();
            __syncthreads();
#pragma unroll
            for (int ks = 0; ks < 8; ++ks) {
                uint32_t af[4];
                ldsm_x4(af, aPc + ks * 32);
#pragma unroll
                for (int p = 0; p < 4; ++p) {
                    uint32_t bf[4];
                    ldsm_x4(bf, bV[p] + ks * 32);
                    mma_tf32(o[2 * p], af, bf[0], bf[1]);
                    mma_tf32(o[2 * p + 1], af, bf[2], bf[3]);
                }
            }
            __syncthreads();
            if (c + 1 < nc) {
                const int ka = kb + (c + 1) * 64;
#pragma unroll
                for (int i = 0; i < 8; ++i)
                    cpa16(vDst + i * (16 * 68 * 4),
                          Vtb + (size_t)(rowV + 16 * i) * Sc + ka + colV);
            } else if (j < bi) {
                const int ka = (j + 1) * BSZ;
#pragma unroll
                for (int i = 0; i < 8; ++i)
                    cpa16(kDst + i * (8 * 132 * 4),
                          Kb + (size_t)(ka + rowK + 8 * i) * Hc + colK);
            }
            cpa_commit();
        }
    }

    // epilogue: tf32-rounded output (feeds raw-bit Wo GEMM)
    const float invn = 1.f / ((float)(bi + 1) + 1e-6f);
#pragma unroll
    for (int u = 0; u < 8; ++u) {
        int d = nh * 64 + 16 * (u >> 1) + 8 * (u & 1) + 2 * tig;
        *(float2*)(O + base + (size_t)qi0 * Hc + d) =
            make_float2(rnd_tf32(o[u][0] * invn), rnd_tf32(o[u][1] * invn));
        *(float2*)(O + base + (size_t)qi1 * Hc + d) =
            make_float2(rnd_tf32(o[u][2] * invn), rnd_tf32(o[u][3] * invn));
    }
}

// ---------------------------------------------------------------------------
extern "C" void kernel_launch(void* const* d_in, const int* in_sizes, int n_in,
                              void* d_out, int out_size) {
    const float* hs = (const float*)d_in[0];
    const float* Wq = (const float*)d_in[1];
    const float* Wk = (const float*)d_in[2];
    const float* Wv = (const float*)d_in[3];
    const float* Wo = (const float*)d_in[4];
    float* out = (float*)d_out;

    float *qp, *kp, *vtp, *aop, *hsr, *wr;
    cudaGetSymbolAddress((void**)&qp, g_q);
    cudaGetSymbolAddress((void**)&kp, g_k);
    cudaGetSymbolAddress((void**)&vtp, g_vt);
    cudaGetSymbolAddress((void**)&aop, g_ao);
    cudaGetSymbolAddress((void**)&hsr, g_hsr);
    cudaGetSymbolAddress((void**)&wr, g_wr);
    float* wor = wr + 3 * (size_t)Hc * Hc;

    static int init_done = 0;
    static cudaStream_t s2;
    static cudaEvent_t evR, ev1;
    if (!init_done) {
        cudaFuncSetAttribute(gemm_qkv, cudaFuncAttributeMaxDynamicSharedMemorySize,
                             GEMM_SMEM);
        cudaFuncSetAttribute(gemm_wo, cudaFuncAttributeMaxDynamicSharedMemorySize,
                             GEMM_SMEM);
        cudaFuncSetAttribute(attn_mma, cudaFuncAttributeMaxDynamicSharedMemorySize,
                             ATTN_SMEM);
        cudaStreamCreateWithFlags(&s2, cudaStreamNonBlocking);
        cudaEventCreateWithFlags(&evR, cudaEventDisableTiming);
        cudaEventCreateWithFlags(&ev1, cudaEventDisableTiming);
        init_done = 1;
    }

    const int nTot4 = (Bc * Sc * Hc + 4 * Hc * Hc) / 4;  // 6M
    round_all<<<nTot4 / 256, 256>>>(hs, Wq, Wk, Wv, Wo, hsr, wr);
    cudaEventRecord(evR, 0);
    cudaStreamWaitEvent(s2, evR, 0);

    dim3 gqh(24, Mc / 256);  // half of QKV: 384 CTAs
    dim3 gah(32, NHc / 2, Bc);
    // half B on second stream (heads 8-15)
    gemm_qkv<<<gqh, 512, GEMM_SMEM, s2>>>(hsr, wr, qp, kp, vtp, 8);
    attn_mma<<<gah, 256, ATTN_SMEM, s2>>>(qp, kp, vtp, aop, 8);
    cudaEventRecord(ev1, s2);
    // half A on default stream (heads 0-7)
    gemm_qkv<<<gqh, 512, GEMM_SMEM>>>(hsr, wr, qp, kp, vtp, 0);
    attn_mma<<<gah, 256, ATTN_SMEM>>>(qp, kp, vtp, aop, 0);
    cudaStreamWaitEvent(0, ev1, 0);

    dim3 gw(Hc / 128, Mc / 256);  // (16, 16)
    gemm_wo<<<gw, 512, GEMM_SMEM>>>(aop, wor, out);
}

// round 15
// speedup vs baseline: 1.0479x; 1.0479x over previous
#include <cuda_runtime.h>
#include <cstdint>
#include <math.h>

// Problem constants
static constexpr int Bc = 2, Sc = 2048, Hc = 2048, NHc = 16, HDc = 128, BSZ = 256;
static constexpr int Mc = Bc * Sc;  // 4096
static constexpr float SCALE = 0.08838834764831845f;  // 1/sqrt(128)

// Scratch (device globals — no allocation allowed)
__device__ float g_q[Bc * Sc * Hc];
__device__ float g_k[Bc * Sc * Hc];
__device__ float g_vt[Bc * Sc * Hc];      // V transposed: [b, h, d, s]
__device__ float g_ao[Bc * Sc * Hc];
__device__ float g_hsr[Bc * Sc * Hc];     // tf32-rounded hidden_states
__device__ float g_wr[4][Hc * Hc];        // tf32-rounded Wq,Wk,Wv,Wo (contiguous)

// ---------------------------------------------------------------------------
// helpers
// ---------------------------------------------------------------------------
__device__ __forceinline__ uint32_t smem_u32(const void* p) {
    uint32_t a;
    asm("{ .reg .u64 t; cvta.to.shared.u64 t, %1; cvt.u32.u64 %0, t; }"
        : "=r"(a) : "l"(p));
    return a;
}
__device__ __forceinline__ uint32_t f2tf32(float x) {
    uint32_t r;
    asm("cvt.rna.tf32.f32 %0, %1;" : "=r"(r) : "f"(x));
    return r;
}
__device__ __forceinline__ float rnd_tf32(float x) {
    return __uint_as_float(f2tf32(x));
}
__device__ __forceinline__ void ldsm_x4(uint32_t* r, uint32_t addr) {
    asm volatile("ldmatrix.sync.aligned.m8n8.x4.shared.b16 {%0,%1,%2,%3}, [%4];"
                 : "=r"(r[0]), "=r"(r[1]), "=r"(r[2]), "=r"(r[3]) : "r"(addr));
}
__device__ __forceinline__ void mma_tf32(float* d, const uint32_t* a,
                                         uint32_t b0, uint32_t b1) {
    asm volatile(
        "mma.sync.aligned.m16n8k8.row.col.f32.tf32.tf32.f32 "
        "{%0,%1,%2,%3}, {%4,%5,%6,%7}, {%8,%9}, {%0,%1,%2,%3};"
        : "+f"(d[0]), "+f"(d[1]), "+f"(d[2]), "+f"(d[3])
        : "r"(a[0]), "r"(a[1]), "r"(a[2]), "r"(a[3]), "r"(b0), "r"(b1));
}
__device__ __forceinline__ void cpa16(uint32_t dst, const void* src) {
    asm volatile("cp.async.cg.shared.global [%0], [%1], 16;"
                 :: "r"(dst), "l"(src) : "memory");
}
__device__ __forceinline__ void cpa_commit() {
    asm volatile("cp.async.commit_group;" ::: "memory");
}
__device__ __forceinline__ void cpa_wait1() {
    asm volatile("cp.async.wait_group 1;" ::: "memory");
}
__device__ __forceinline__ void cpa_wait0() {
    asm volatile("cp.async.wait_group 0;" ::: "memory");
}

// ---------------------------------------------------------------------------
// tf32 pre-rounding, all 5 tensors in one launch.
// ---------------------------------------------------------------------------
__global__ __launch_bounds__(256) void round_all(const float* __restrict__ hs,
                                                 const float* __restrict__ Wq,
                                                 const float* __restrict__ Wk,
                                                 const float* __restrict__ Wv,
                                                 const float* __restrict__ Wo,
                                                 float* __restrict__ hsr,
                                                 float* __restrict__ wr) {
    const int nHS4 = Bc * Sc * Hc / 4;   // 2M
    const int nW4 = Hc * Hc / 4;         // 1M
    int i = blockIdx.x * blockDim.x + threadIdx.x;
    const float4* src;
    float4* dst;
    int idx;
    if (i < nHS4) {
        src = (const float4*)hs; dst = (float4*)hsr; idx = i;
    } else {
        int j = i - nHS4;
        int w = j / nW4;
        idx = j - w * nW4;
        src = (const float4*)(w == 0 ? Wq : w == 1 ? Wk : w == 2 ? Wv : Wo);
        dst = (float4*)wr + (size_t)w * nW4;
    }
    float4 v = src[idx];
    float4 r;
    r.x = rnd_tf32(v.x); r.y = rnd_tf32(v.y);
    r.z = rnd_tf32(v.z); r.w = rnd_tf32(v.w);
    dst[idx] = r;
}

// ---------------------------------------------------------------------------
// GEMM machinery: R10 configuration (128x128 tile, 256 threads, 2 CTA/SM,
// 3-stage cp.async). Validated fastest GEMM config.
// ---------------------------------------------------------------------------
static constexpr int RSF = 36;
static constexpr int ATILE = 128 * RSF * 4;        // 18432 bytes
static constexpr int STAGE = 2 * ATILE;            // 36864 bytes
static constexpr int GEMM_SMEM = 3 * STAGE;        // 110592 bytes
static constexpr int KD = 2048;
static constexpr int NKBg = KD / 32;               // 64

struct GemmCore {
    uint32_t sb;
    const float* gA0;
    const float* gB0;
    uint32_t so0;
    uint32_t aFragOff, bFragOff;
    float acc[4][4][4];

    __device__ __forceinline__ void init(uint32_t sb_, const float* A, const float* W,
                                         int m0, int n0, int tid) {
        sb = sb_;
        const int lane = tid & 31, wid = tid >> 5;
        const int wm = wid >> 2, wn = wid & 3;
        const int row = tid >> 3, ch = tid & 7;
        gA0 = A + (size_t)(m0 + row) * KD + ch * 4;
        gB0 = W + (size_t)(n0 + row) * KD + ch * 4;
        so0 = row * (RSF * 4) + ch * 16;
        const int arow = wm * 64 + (lane & 7) + ((lane >> 3) & 1) * 8;
        aFragOff = arow * (RSF * 4) + ((lane >> 4) & 1) * 16;
        const int brow = wn * 32 + (lane & 7) + ((lane >> 4) & 1) * 8;
        bFragOff = brow * (RSF * 4) + ((lane >> 3) & 1) * 16;
#pragma unroll
        for (int t = 0; t < 4; ++t)
#pragma unroll
            for (int u = 0; u < 4; ++u)
#pragma unroll
                for (int e = 0; e < 4; ++e) acc[t][u][e] = 0.f;
    }

    __device__ __forceinline__ void ld_stage(uint32_t st, int kb) {
#pragma unroll
        for (int i = 0; i < 4; ++i) {
            cpa16(st + so0 + i * (32 * RSF * 4), gA0 + kb * 32 + i * (32 * KD));
            cpa16(st + ATILE + so0 + i * (32 * RSF * 4), gB0 + kb * 32 + i * (32 * KD));
        }
        cpa_commit();
    }

    __device__ __forceinline__ void run() {
        ld_stage(sb, 0);
        ld_stage(sb + STAGE, 1);
        int stage = 0;
        for (int kb = 0; kb < NKBg; ++kb) {
            cpa_wait1();
            __syncthreads();
            {
                int ns = stage + 2;
                if (ns >= 3) ns -= 3;
                if (kb + 2 < NKBg) {
                    ld_stage(sb + ns * STAGE, kb + 2);
                } else {
                    cpa_commit();
                }
            }
            const uint32_t sA = sb + stage * STAGE;
            const uint32_t sB = sA + ATILE;
#pragma unroll
            for (int ks = 0; ks < 4; ++ks) {
                uint32_t af[4][4];
#pragma unroll
                for (int t = 0; t < 4; ++t)
                    ldsm_x4(af[t], sA + aFragOff + t * (16 * RSF * 4) + ks * 32);
                uint32_t bf[2][4];
#pragma unroll
                for (int p = 0; p < 2; ++p)
                    ldsm_x4(bf[p], sB + bFragOff + p * (16 * RSF * 4) + ks * 32);
#pragma unroll
                for (int t = 0; t < 4; ++t) {
                    mma_tf32(acc[t][0], af[t], bf[0][0], bf[0][1]);
                    mma_tf32(acc[t][1], af[t], bf[0][2], bf[0][3]);
                    mma_tf32(acc[t][2], af[t], bf[1][0], bf[1][1]);
                    mma_tf32(acc[t][3], af[t], bf[1][2], bf[1][3]);
                }
            }
            if (++stage == 3) stage = 0;
        }
    }
};

// Merged Q/K/V projection GEMM, half of heads per launch.
// grid (24, 32): bx>>3 = widx (0=Q,1=K,2=V), (bx&7)+ntOff = head; by = m-tile(128).
__global__ __launch_bounds__(256, 2) void gemm_qkv(const float* __restrict__ A,
                                                   const float* __restrict__ Wbase,
                                                   float* __restrict__ Qo,
                                                   float* __restrict__ Ko,
                                                   float* __restrict__ Vto,
                                                   int ntOff) {
    extern __shared__ __align__(128) char smem[];
    const int tid = threadIdx.x;
    const int widx = blockIdx.x >> 3;
    const int n0 = ((blockIdx.x & 7) + ntOff) * 128;
    const int m0 = blockIdx.y * 128;
    const float* W = Wbase + (size_t)widx * Hc * Hc;

    GemmCore gc;
    gc.init(smem_u32(smem), A, W, m0, n0, tid);
    gc.run();

    const int lane = tid & 31, wid = tid >> 5;
    const int wm = wid >> 2, wn = wid & 3;
    const int crow = lane >> 2, ccol = (lane & 3) * 2;
    if (widx == 2) {
        // V: write transposed per head [b,h,d,s], tf32-rounded
#pragma unroll
        for (int t = 0; t < 4; ++t) {
            int r0 = m0 + wm * 64 + t * 16 + crow;
#pragma unroll
            for (int u = 0; u < 4; ++u) {
                int c = n0 + wn * 32 + u * 8 + ccol;
#pragma unroll
                for (int e = 0; e < 4; ++e) {
                    int r = r0 + (e >> 1) * 8;
                    int cc = c + (e & 1);
                    int bq = r >> 11, s = r & 2047;
                    int hh = cc >> 7, d = cc & 127;
                    Vto[(((size_t)bq * NHc + hh) * HDc + d) * Sc + s] =
                        rnd_tf32(gc.acc[t][u][e]);
                }
            }
        }
    } else {
        float* C = (widx == 0) ? Qo : Ko;
#pragma unroll
        for (int t = 0; t < 4; ++t) {
            int r0 = m0 + wm * 64 + t * 16 + crow;
#pragma unroll
            for (int u = 0; u < 4; ++u) {
                int c = n0 + wn * 32 + u * 8 + ccol;
                *(float2*)(C + (size_t)r0 * Hc + c) =
                    make_float2(rnd_tf32(gc.acc[t][u][0]), rnd_tf32(gc.acc[t][u][1]));
                *(float2*)(C + (size_t)(r0 + 8) * Hc + c) =
                    make_float2(rnd_tf32(gc.acc[t][u][2]), rnd_tf32(gc.acc[t][u][3]));
            }
        }
    }
}

// Output projection GEMM (plain fp32 epilogue). grid (16, 32).
__global__ __launch_bounds__(256, 2) void gemm_wo(const float* __restrict__ A,
                                                  const float* __restrict__ W,
                                                  float* __restrict__ C) {
    extern __shared__ __align__(128) char smem[];
    const int tid = threadIdx.x;
    const int n0 = blockIdx.x * 128;
    const int m0 = blockIdx.y * 128;

    GemmCore gc;
    gc.init(smem_u32(smem), A, W, m0, n0, tid);
    gc.run();

    const int lane = tid & 31, wid = tid >> 5;
    const int wm = wid >> 2, wn = wid & 3;
    const int crow = lane >> 2, ccol = (lane & 3) * 2;
#pragma unroll
    for (int t = 0; t < 4; ++t) {
        int r0 = m0 + wm * 64 + t * 16 + crow;
#pragma unroll
        for (int u = 0; u < 4; ++u) {
            int c = n0 + wn * 32 + u * 8 + ccol;
            *(float2*)(C + (size_t)r0 * Hc + c) =
                make_float2(gc.acc[t][u][0], gc.acc[t][u][1]);
            *(float2*)(C + (size_t)(r0 + 8) * Hc + c) =
                make_float2(gc.acc[t][u][2], gc.acc[t][u][3]);
        }
    }
}

// ---------------------------------------------------------------------------
// Tensor-core block-softmax attention, 2-CTA/SM, double-buffered KV.
// smem (floats): Q[64*132]=8448 | KV0[8448] | KV1[8448] | Pc[64*36]=2304 | red[256]
//   = 27904 floats = 111616 B  -> 2 CTAs/SM.
// QK: 64-key K chunks ping-pong; prefetch issued before compute (1 sync/chunk).
// PV: 32-key V chunks (128x36) ping-pong in the same buffers; P staged per
//     chunk in Pc (2 syncs/chunk). Key accumulation order identical to R10.
// ---------------------------------------------------------------------------
static constexpr int AQ = 0;
static constexpr int AKV0 = 8448;
static constexpr int AKV1 = 16896;
static constexpr int APc = 25344;
static constexpr int ARED = 27648;
static constexpr int ATTN_SMEM = 27904 * 4;  // 111616 bytes

__global__ __launch_bounds__(256, 2) void attn_mma(const float* __restrict__ Q,
                                                   const float* __restrict__ K,
                                                   const float* __restrict__ Vt,
                                                   float* __restrict__ O,
                                                   int hOff) {
    extern __shared__ __align__(1024) float sma[];
    const uint32_t sb = smem_u32(sma);
    const int tid = threadIdx.x, lane = tid & 31, wid = tid >> 5;
    const int ms = wid >> 1, nh = wid & 1, g = lane >> 2, tig = lane & 3;
    const int qt = 31 - blockIdx.x;  // heavy tiles first
    const int h = blockIdx.y + hOff, b = blockIdx.z;
    const int q0 = qt * 64, bi = qt >> 2, sp = qt & 3;
    const size_t base = (size_t)b * Sc * Hc + (size_t)h * HDc;
    const float* Kb = K + base;
    const float* Qb = Q + base;
    const float* Vtb = Vt + ((size_t)(b * NHc + h) * HDc) * Sc;

    // load-slot geometry
    const int rowK = tid >> 5, colK = (tid & 31) * 4;    // K chunk: 64r x 128d
    const int rowV = tid >> 3, colV = (tid & 7) * 4;     // V chunk: 128d x 32k
    const uint32_t kRel = (uint32_t)(rowK * 132 + colK) * 4;
    const uint32_t vRel = (uint32_t)(rowV * 36 + colV) * 4;

    // prologue: Q tile + K block0 chunk0 into KV0 (one group)
#pragma unroll
    for (int i = 0; i < 8; ++i)
        cpa16(sb + (AQ + (rowK + 8 * i) * 132 + colK) * 4,
              Qb + (size_t)(q0 + rowK + 8 * i) * Hc + colK);
#pragma unroll
    for (int i = 0; i < 8; ++i)
        cpa16(sb + AKV0 * 4 + kRel + i * (8 * 132 * 4),
              Kb + (size_t)(rowK + 8 * i) * Hc + colK);
    cpa_commit();

    // fragment bases
    const int frow = (lane & 7) + ((lane >> 3) & 1) * 8;
    const uint32_t aQ = sb + ((AQ + (ms * 16 + frow) * 132 + ((lane >> 4) & 1) * 4) * 4);
    const int browk = (lane & 7) + ((lane >> 4) & 1) * 8;
    const uint32_t bcolk = ((lane >> 3) & 1) * 4;
    const uint32_t bK0rel = ((nh * 32 + browk) * 132 + bcolk) * 4;
    const uint32_t bK1rel = bK0rel + 16 * 132 * 4;
    const uint32_t aPc = sb + ((APc + (ms * 16 + frow) * 36 + ((lane >> 4) & 1) * 4) * 4);
    uint32_t bVrel[4];
#pragma unroll
    for (int p = 0; p < 4; ++p)
        bVrel[p] = ((nh * 64 + p * 16 + browk) * 36 + bcolk) * 4;

    float o[8][4];
#pragma unroll
    for (int u = 0; u < 8; ++u)
#pragma unroll
        for (int e = 0; e < 4; ++e) o[u][e] = 0.f;

    int cur = 0;  // buffer holding the chunk about to be computed
    const int row0 = ms * 16 + g;
    const int qi0 = q0 + row0, qi1 = qi0 + 8;

    for (int j = 0; j <= bi; ++j) {
        const int nc = (j < bi) ? 4 : (sp + 1);
        const int kb = j * BSZ;
        float s[16][4];
#pragma unroll
        for (int t = 0; t < 16; ++t)
#pragma unroll
            for (int e = 0; e < 4; ++e) s[t][e] = 0.f;

        // ---- QK chunks: wait -> sync -> prefetch(other buf) -> compute ----
        for (int c = 0; c < nc; ++c) {
            cpa_wait0();
            __syncthreads();
            const uint32_t nb = sb + (cur ? AKV0 : AKV1) * 4;  // other buffer
            if (c + 1 < nc) {
                const int ka = kb + (c + 1) * 64;
#pragma unroll
                for (int i = 0; i < 8; ++i)
                    cpa16(nb + kRel + i * (8 * 132 * 4),
                          Kb + (size_t)(ka + rowK + 8 * i) * Hc + colK);
            } else {
                // first 32-key V chunk of this block
#pragma unroll
                for (int i = 0; i < 4; ++i)
                    cpa16(nb + vRel + i * (32 * 36 * 4),
                          Vtb + (size_t)(rowV + 32 * i) * Sc + kb + colV);
            }
            cpa_commit();

            const uint32_t bufb = sb + (cur ? AKV1 : AKV0) * 4;
#pragma unroll
            for (int ks = 0; ks < 16; ++ks) {
                uint32_t af[4];
                ldsm_x4(af, aQ + ks * 32);
                uint32_t bf[4];
                ldsm_x4(bf, bufb + bK0rel + ks * 32);
                mma_tf32(s[c * 4 + 0], af, bf[0], bf[1]);
                mma_tf32(s[c * 4 + 1], af, bf[2], bf[3]);
                ldsm_x4(bf, bufb + bK1rel + ks * 32);
                mma_tf32(s[c * 4 + 2], af, bf[0], bf[1]);
                mma_tf32(s[c * 4 + 3], af, bf[2], bf[3]);
            }
            cur ^= 1;
        }

        // ---- per-block softmax (unchanged numerics) ----
        const bool diag = (j == bi);
        const int ntile = nc * 4;
        float mx0 = -1e30f, mx1 = -1e30f;
        for (int t = 0; t < ntile; ++t) {
            if (diag) {
                int col = kb + 64 * (t >> 2) + nh * 32 + 8 * (t & 3) + 2 * tig;
                if (col > qi0) s[t][0] = -1e30f;
                if (col + 1 > qi0) s[t][1] = -1e30f;
                if (col > qi1) s[t][2] = -1e30f;
                if (col + 1 > qi1) s[t][3] = -1e30f;
            }
            mx0 = fmaxf(mx0, fmaxf(s[t][0], s[t][1]));
            mx1 = fmaxf(mx1, fmaxf(s[t][2], s[t][3]));
        }
        mx0 = fmaxf(mx0, __shfl_xor_sync(0xffffffffu, mx0, 1));
        mx0 = fmaxf(mx0, __shfl_xor_sync(0xffffffffu, mx0, 2));
        mx1 = fmaxf(mx1, __shfl_xor_sync(0xffffffffu, mx1, 1));
        mx1 = fmaxf(mx1, __shfl_xor_sync(0xffffffffu, mx1, 2));
        float l0 = 0.f, l1 = 0.f;
        for (int t = 0; t < ntile; ++t) {
            float p0 = (s[t][0] <= -1e29f) ? 0.f : __expf(SCALE * (s[t][0] - mx0));
            float p1 = (s[t][1] <= -1e29f) ? 0.f : __expf(SCALE * (s[t][1] - mx0));
            float p2 = (s[t][2] <= -1e29f) ? 0.f : __expf(SCALE * (s[t][2] - mx1));
            float p3 = (s[t][3] <= -1e29f) ? 0.f : __expf(SCALE * (s[t][3] - mx1));
            s[t][0] = p0; s[t][1] = p1; s[t][2] = p2; s[t][3] = p3;
            l0 += p0 + p1;
            l1 += p2 + p3;
        }
        l0 += __shfl_xor_sync(0xffffffffu, l0, 1);
        l0 += __shfl_xor_sync(0xffffffffu, l0, 2);
        l1 += __shfl_xor_sync(0xffffffffu, l1, 1);
        l1 += __shfl_xor_sync(0xffffffffu, l1, 2);
        if (tig == 0) {
            sma[ARED + row0 * 2 + nh] = mx0;
            sma[ARED + 128 + row0 * 2 + nh] = l0;
            sma[ARED + (row0 + 8) * 2 + nh] = mx1;
            sma[ARED + 128 + (row0 + 8) * 2 + nh] = l1;
        }
        __syncthreads();
        float f0, f1;
        {
            float mo0 = sma[ARED + row0 * 2 + (nh ^ 1)];
            float lo0 = sma[ARED + 128 + row0 * 2 + (nh ^ 1)];
            float mo1 = sma[ARED + (row0 + 8) * 2 + (nh ^ 1)];
            float lo1 = sma[ARED + 128 + (row0 + 8) * 2 + (nh ^ 1)];
            float M0 = fmaxf(mx0, mo0), M1 = fmaxf(mx1, mo1);
            float cc0 = __expf(SCALE * (mx0 - M0)), co0 = __expf(SCALE * (mo0 - M0));
            float cc1 = __expf(SCALE * (mx1 - M1)), co1 = __expf(SCALE * (mo1 - M1));
            f0 = cc0 / (l0 * cc0 + lo0 * co0 + 1e-30f);
            f1 = cc1 / (l1 * cc1 + lo1 * co1 + 1e-30f);
        }

        // ---- PV: 32-key chunks; P staged per chunk; V prefetched ----
        const int nv = nc * 2;
        for (int c2 = 0; c2 < nv; ++c2) {
            const int kg = c2 >> 1, hh = c2 & 1;
            // stage P for this 32-key chunk (owning half only)
            if (nh == hh) {
#pragma unroll
                for (int tt = 0; tt < 4; ++tt) {
                    int t = kg * 4 + tt;
                    int col = 8 * tt + 2 * tig;
                    uint32_t a0 = sb + (APc + (ms * 16 + g) * 36 + col) * 4;
                    asm volatile("st.shared.v2.b32 [%0], {%1,%2};"
                                 :: "r"(a0), "r"(f2tf32(s[t][0] * f0)),
                                    "r"(f2tf32(s[t][1] * f0)) : "memory");
                    asm volatile("st.shared.v2.b32 [%0], {%1,%2};"
                                 :: "r"(a0 + 8 * 36 * 4), "r"(f2tf32(s[t][2] * f1)),
                                    "r"(f2tf32(s[t][3] * f1)) : "memory");
                }
            }
            cpa_wait0();
            __syncthreads();  // V chunk arrived + P visible
            const uint32_t nb = sb + (cur ? AKV0 : AKV1) * 4;
            if (c2 + 1 < nv) {
                const int ka = kb + (c2 + 1) * 32;
#pragma unroll
                for (int i = 0; i < 4; ++i)
                    cpa16(nb + vRel + i * (32 * 36 * 4),
                          Vtb + (size_t)(rowV + 32 * i) * Sc + ka + colV);
            } else if (j < bi) {
                const int ka = (j + 1) * BSZ;
#pragma unroll
                for (int i = 0; i < 8; ++i)
                    cpa16(nb + kRel + i * (8 * 132 * 4),
                          Kb + (size_t)(ka + rowK + 8 * i) * Hc + colK);
            }
            cpa_commit();

            const uint32_t bufb = sb + (cur ? AKV1 : AKV0) * 4;
#pragma unroll
            for (int ks = 0; ks < 4; ++ks) {
                uint32_t af[4];
                ldsm_x4(af, aPc + ks * 32);
#pragma unroll
                for (int p = 0; p < 4; ++p) {
                    uint32_t bf[4];
                    ldsm_x4(bf, bufb + bVrel[p] + ks * 32);
                    mma_tf32(o[2 * p], af, bf[0], bf[1]);
                    mma_tf32(o[2 * p + 1], af, bf[2], bf[3]);
                }
            }
            __syncthreads();  // Pc safe to rewrite next chunk
            cur ^= 1;
        }
    }

    // epilogue: tf32-rounded output (feeds raw-bit Wo GEMM)
    const float invn = 1.f / ((float)(bi + 1) + 1e-6f);
#pragma unroll
    for (int u = 0; u < 8; ++u) {
        int d = nh * 64 + 16 * (u >> 1) + 8 * (u & 1) + 2 * tig;
        *(float2*)(O + base + (size_t)qi0 * Hc + d) =
            make_float2(rnd_tf32(o[u][0] * invn), rnd_tf32(o[u][1] * invn));
        *(float2*)(O + base + (size_t)qi1 * Hc + d) =
            make_float2(rnd_tf32(o[u][2] * invn), rnd_tf32(o[u][3] * invn));
    }
}

// ---------------------------------------------------------------------------
extern "C" void kernel_launch(void* const* d_in, const int* in_sizes, int n_in,
                              void* d_out, int out_size) {
    const float* hs = (const float*)d_in[0];
    const float* Wq = (const float*)d_in[1];
    const float* Wk = (const float*)d_in[2];
    const float* Wv = (const float*)d_in[3];
    const float* Wo = (const float*)d_in[4];
    float* out = (float*)d_out;

    float *qp, *kp, *vtp, *aop, *hsr, *wr;
    cudaGetSymbolAddress((void**)&qp, g_q);
    cudaGetSymbolAddress((void**)&kp, g_k);
    cudaGetSymbolAddress((void**)&vtp, g_vt);
    cudaGetSymbolAddress((void**)&aop, g_ao);
    cudaGetSymbolAddress((void**)&hsr, g_hsr);
    cudaGetSymbolAddress((void**)&wr, g_wr);
    float* wor = wr + 3 * (size_t)Hc * Hc;

    static int init_done = 0;
    static cudaStream_t s2;
    static cudaEvent_t evR, ev1;
    if (!init_done) {
        cudaFuncSetAttribute(gemm_qkv, cudaFuncAttributeMaxDynamicSharedMemorySize,
                             GEMM_SMEM);
        cudaFuncSetAttribute(gemm_wo, cudaFuncAttributeMaxDynamicSharedMemorySize,
                             GEMM_SMEM);
        cudaFuncSetAttribute(attn_mma, cudaFuncAttributeMaxDynamicSharedMemorySize,
                             ATTN_SMEM);
        cudaStreamCreateWithFlags(&s2, cudaStreamNonBlocking);
        cudaEventCreateWithFlags(&evR, cudaEventDisableTiming);
        cudaEventCreateWithFlags(&ev1, cudaEventDisableTiming);
        init_done = 1;
    }

    const int nTot4 = (Bc * Sc * Hc + 4 * Hc * Hc) / 4;  // 6M
    round_all<<<nTot4 / 256, 256>>>(hs, Wq, Wk, Wv, Wo, hsr, wr);
    cudaEventRecord(evR, 0);
    cudaStreamWaitEvent(s2, evR, 0);

    dim3 gqh(24, Mc / 128);  // half of QKV: 768 CTAs
    dim3 gah(32, NHc / 2, Bc);
    // half B on second stream (heads 8-15)
    gemm_qkv<<<gqh, 256, GEMM_SMEM, s2>>>(hsr, wr, qp, kp, vtp, 8);
    attn_mma<<<gah, 256, ATTN_SMEM, s2>>>(qp, kp, vtp, aop, 8);
    cudaEventRecord(ev1, s2);
    // half A on default stream (heads 0-7)
    gemm_qkv<<<gqh, 256, GEMM_SMEM>>>(hsr, wr, qp, kp, vtp, 0);
    attn_mma<<<gah, 256, ATTN_SMEM>>>(qp, kp, vtp, aop, 0);
    cudaStreamWaitEvent(0, ev1, 0);

    dim3 gw(Hc / 128, Mc / 128);  // (16, 32)
    gemm_wo<<<gw, 256, GEMM_SMEM>>>(aop, wor, out);
}

// round 17
// speedup vs baseline: 1.0652x; 1.0164x over previous
#include <cuda_runtime.h>
#include <cstdint>
#include <math.h>

// Problem constants
static constexpr int Bc = 2, Sc = 2048, Hc = 2048, NHc = 16, HDc = 128, BSZ = 256;
static constexpr int Mc = Bc * Sc;  // 4096
static constexpr float SCALE = 0.08838834764831845f;  // 1/sqrt(128)

// Scratch (device globals — no allocation allowed)
__device__ float g_q[Bc * Sc * Hc];
__device__ float g_k[Bc * Sc * Hc];
__device__ float g_vt[Bc * Sc * Hc];      // V transposed: [b, h, d, s]
__device__ float g_ao[Bc * Sc * Hc];
__device__ float g_hsr[Bc * Sc * Hc];     // tf32-rounded hidden_states
__device__ float g_wr[4][Hc * Hc];        // tf32-rounded Wq,Wk,Wv,Wo (contiguous)

// ---------------------------------------------------------------------------
// helpers
// ---------------------------------------------------------------------------
__device__ __forceinline__ uint32_t smem_u32(const void* p) {
    uint32_t a;
    asm("{ .reg .u64 t; cvta.to.shared.u64 t, %1; cvt.u32.u64 %0, t; }"
        : "=r"(a) : "l"(p));
    return a;
}
__device__ __forceinline__ uint32_t f2tf32(float x) {
    uint32_t r;
    asm("cvt.rna.tf32.f32 %0, %1;" : "=r"(r) : "f"(x));
    return r;
}
__device__ __forceinline__ float rnd_tf32(float x) {
    return __uint_as_float(f2tf32(x));
}
__device__ __forceinline__ void ldsm_x4(uint32_t* r, uint32_t addr) {
    asm volatile("ldmatrix.sync.aligned.m8n8.x4.shared.b16 {%0,%1,%2,%3}, [%4];"
                 : "=r"(r[0]), "=r"(r[1]), "=r"(r[2]), "=r"(r[3]) : "r"(addr));
}
__device__ __forceinline__ void mma_tf32(float* d, const uint32_t* a,
                                         uint32_t b0, uint32_t b1) {
    asm volatile(
        "mma.sync.aligned.m16n8k8.row.col.f32.tf32.tf32.f32 "
        "{%0,%1,%2,%3}, {%4,%5,%6,%7}, {%8,%9}, {%0,%1,%2,%3};"
        : "+f"(d[0]), "+f"(d[1]), "+f"(d[2]), "+f"(d[3])
        : "r"(a[0]), "r"(a[1]), "r"(a[2]), "r"(a[3]), "r"(b0), "r"(b1));
}
__device__ __forceinline__ void cpa16(uint32_t dst, const void* src) {
    asm volatile("cp.async.cg.shared.global [%0], [%1], 16;"
                 :: "r"(dst), "l"(src) : "memory");
}
__device__ __forceinline__ void cpa_commit() {
    asm volatile("cp.async.commit_group;" ::: "memory");
}
__device__ __forceinline__ void cpa_wait1() {
    asm volatile("cp.async.wait_group 1;" ::: "memory");
}
__device__ __forceinline__ void cpa_wait0() {
    asm volatile("cp.async.wait_group 0;" ::: "memory");
}

// ---------------------------------------------------------------------------
// tf32 pre-rounding, all 5 tensors in one launch. MLP=4 per thread.
// Each block covers an aligned 1024-float4 span (single region per block).
// ---------------------------------------------------------------------------
__global__ __launch_bounds__(256) void round_all(const float* __restrict__ hs,
                                                 const float* __restrict__ Wq,
                                                 const float* __restrict__ Wk,
                                                 const float* __restrict__ Wv,
                                                 const float* __restrict__ Wo,
                                                 float* __restrict__ hsr,
                                                 float* __restrict__ wr) {
    const int nHS4 = Bc * Sc * Hc / 4;   // 2M
    int base = blockIdx.x * 1024 + threadIdx.x;
    const float4* src;
    float4* dst;
    int off;
    if (base < nHS4) {
        src = (const float4*)hs; dst = (float4*)hsr; off = base;
    } else {
        int j = base - nHS4;
        int w = j >> 20;                 // nW4 = 1M = 1<<20
        off = j & 0xFFFFF;
        src = (const float4*)(w == 0 ? Wq : w == 1 ? Wk : w == 2 ? Wv : Wo);
        dst = (float4*)wr + ((size_t)w << 20);
    }
#pragma unroll
    for (int k2 = 0; k2 < 4; ++k2) {
        float4 v = src[off + k2 * 256];
        float4 r;
        r.x = rnd_tf32(v.x); r.y = rnd_tf32(v.y);
        r.z = rnd_tf32(v.z); r.w = rnd_tf32(v.w);
        dst[off + k2 * 256] = r;
    }
}

// ---------------------------------------------------------------------------
// GEMM machinery: R10 configuration (128x128 tile, 256 threads, 2 CTA/SM,
// 3-stage cp.async). Validated fastest GEMM config.
// ---------------------------------------------------------------------------
static constexpr int RSF = 36;
static constexpr int ATILE = 128 * RSF * 4;        // 18432 bytes
static constexpr int STAGE = 2 * ATILE;            // 36864 bytes
static constexpr int GEMM_SMEM = 3 * STAGE;        // 110592 bytes
static constexpr int KD = 2048;
static constexpr int NKBg = KD / 32;               // 64

struct GemmCore {
    uint32_t sb;
    const float* gA0;
    const float* gB0;
    uint32_t so0;
    uint32_t aFragOff, bFragOff;
    float acc[4][4][4];

    __device__ __forceinline__ void init(uint32_t sb_, const float* A, const float* W,
                                         int m0, int n0, int tid) {
        sb = sb_;
        const int lane = tid & 31, wid = tid >> 5;
        const int wm = wid >> 2, wn = wid & 3;
        const int row = tid >> 3, ch = tid & 7;
        gA0 = A + (size_t)(m0 + row) * KD + ch * 4;
        gB0 = W + (size_t)(n0 + row) * KD + ch * 4;
        so0 = row * (RSF * 4) + ch * 16;
        const int arow = wm * 64 + (lane & 7) + ((lane >> 3) & 1) * 8;
        aFragOff = arow * (RSF * 4) + ((lane >> 4) & 1) * 16;
        const int brow = wn * 32 + (lane & 7) + ((lane >> 4) & 1) * 8;
        bFragOff = brow * (RSF * 4) + ((lane >> 3) & 1) * 16;
#pragma unroll
        for (int t = 0; t < 4; ++t)
#pragma unroll
            for (int u = 0; u < 4; ++u)
#pragma unroll
                for (int e = 0; e < 4; ++e) acc[t][u][e] = 0.f;
    }

    __device__ __forceinline__ void ld_stage(uint32_t st, int kb) {
#pragma unroll
        for (int i = 0; i < 4; ++i) {
            cpa16(st + so0 + i * (32 * RSF * 4), gA0 + kb * 32 + i * (32 * KD));
            cpa16(st + ATILE + so0 + i * (32 * RSF * 4), gB0 + kb * 32 + i * (32 * KD));
        }
        cpa_commit();
    }

    __device__ __forceinline__ void run() {
        ld_stage(sb, 0);
        ld_stage(sb + STAGE, 1);
        int stage = 0;
        for (int kb = 0; kb < NKBg; ++kb) {
            cpa_wait1();
            __syncthreads();
            {
                int ns = stage + 2;
                if (ns >= 3) ns -= 3;
                if (kb + 2 < NKBg) {
                    ld_stage(sb + ns * STAGE, kb + 2);
                } else {
                    cpa_commit();
                }
            }
            const uint32_t sA = sb + stage * STAGE;
            const uint32_t sB = sA + ATILE;
#pragma unroll
            for (int ks = 0; ks < 4; ++ks) {
                uint32_t af[4][4];
#pragma unroll
                for (int t = 0; t < 4; ++t)
                    ldsm_x4(af[t], sA + aFragOff + t * (16 * RSF * 4) + ks * 32);
                uint32_t bf[2][4];
#pragma unroll
                for (int p = 0; p < 2; ++p)
                    ldsm_x4(bf[p], sB + bFragOff + p * (16 * RSF * 4) + ks * 32);
#pragma unroll
                for (int t = 0; t < 4; ++t) {
                    mma_tf32(acc[t][0], af[t], bf[0][0], bf[0][1]);
                    mma_tf32(acc[t][1], af[t], bf[0][2], bf[0][3]);
                    mma_tf32(acc[t][2], af[t], bf[1][0], bf[1][1]);
                    mma_tf32(acc[t][3], af[t], bf[1][2], bf[1][3]);
                }
            }
            if (++stage == 3) stage = 0;
        }
    }
};

// Merged Q/K/V projection GEMM, half of heads per launch.
__global__ __launch_bounds__(256, 2) void gemm_qkv(const float* __restrict__ A,
                                                   const float* __restrict__ Wbase,
                                                   float* __restrict__ Qo,
                                                   float* __restrict__ Ko,
                                                   float* __restrict__ Vto,
                                                   int ntOff) {
    extern __shared__ __align__(128) char smem[];
    const int tid = threadIdx.x;
    const int widx = blockIdx.x >> 3;
    const int n0 = ((blockIdx.x & 7) + ntOff) * 128;
    const int m0 = blockIdx.y * 128;
    const float* W = Wbase + (size_t)widx * Hc * Hc;

    GemmCore gc;
    gc.init(smem_u32(smem), A, W, m0, n0, tid);
    gc.run();

    const int lane = tid & 31, wid = tid >> 5;
    const int wm = wid >> 2, wn = wid & 3;
    const int crow = lane >> 2, ccol = (lane & 3) * 2;
    if (widx == 2) {
#pragma unroll
        for (int t = 0; t < 4; ++t) {
            int r0 = m0 + wm * 64 + t * 16 + crow;
#pragma unroll
            for (int u = 0; u < 4; ++u) {
                int c = n0 + wn * 32 + u * 8 + ccol;
#pragma unroll
                for (int e = 0; e < 4; ++e) {
                    int r = r0 + (e >> 1) * 8;
                    int cc = c + (e & 1);
                    int bq = r >> 11, s = r & 2047;
                    int hh = cc >> 7, d = cc & 127;
                    Vto[(((size_t)bq * NHc + hh) * HDc + d) * Sc + s] =
                        rnd_tf32(gc.acc[t][u][e]);
                }
            }
        }
    } else {
        float* C = (widx == 0) ? Qo : Ko;
#pragma unroll
        for (int t = 0; t < 4; ++t) {
            int r0 = m0 + wm * 64 + t * 16 + crow;
#pragma unroll
            for (int u = 0; u < 4; ++u) {
                int c = n0 + wn * 32 + u * 8 + ccol;
                *(float2*)(C + (size_t)r0 * Hc + c) =
                    make_float2(rnd_tf32(gc.acc[t][u][0]), rnd_tf32(gc.acc[t][u][1]));
                *(float2*)(C + (size_t)(r0 + 8) * Hc + c) =
                    make_float2(rnd_tf32(gc.acc[t][u][2]), rnd_tf32(gc.acc[t][u][3]));
            }
        }
    }
}

// Output projection GEMM (plain fp32 epilogue). grid (16, 32).
__global__ __launch_bounds__(256, 2) void gemm_wo(const float* __restrict__ A,
                                                  const float* __restrict__ W,
                                                  float* __restrict__ C) {
    extern __shared__ __align__(128) char smem[];
    const int tid = threadIdx.x;
    const int n0 = blockIdx.x * 128;
    const int m0 = blockIdx.y * 128;

    GemmCore gc;
    gc.init(smem_u32(smem), A, W, m0, n0, tid);
    gc.run();

    const int lane = tid & 31, wid = tid >> 5;
    const int wm = wid >> 2, wn = wid & 3;
    const int crow = lane >> 2, ccol = (lane & 3) * 2;
#pragma unroll
    for (int t = 0; t < 4; ++t) {
        int r0 = m0 + wm * 64 + t * 16 + crow;
#pragma unroll
        for (int u = 0; u < 4; ++u) {
            int c = n0 + wn * 32 + u * 8 + ccol;
            *(float2*)(C + (size_t)r0 * Hc + c) =
                make_float2(gc.acc[t][u][0], gc.acc[t][u][1]);
            *(float2*)(C + (size_t)(r0 + 8) * Hc + c) =
                make_float2(gc.acc[t][u][2], gc.acc[t][u][3]);
        }
    }
}

// ---------------------------------------------------------------------------
// Tensor-core block-softmax attention, 2-CTA/SM, double-buffered KV.
// P chunks live in the slack of the KV buffer holding their V chunk
// (V chunk = 128x36 = 4608 floats of the 8448-float buffer; P at +4608).
// This removes the per-PV-chunk trailing sync: 1 sync per chunk total.
// smem (floats): Q[8448] | KV0[8448] | KV1[8448] | red[256] = 25600 = 102400 B
// ---------------------------------------------------------------------------
static constexpr int AQ = 0;
static constexpr int AKV0 = 8448;
static constexpr int AKV1 = 16896;
static constexpr int ARED = 25344;
static constexpr int ATTN_SMEM = 25600 * 4;  // 102400 bytes
static constexpr int PSL = 4608;             // P offset within KV buffer (floats)

__global__ __launch_bounds__(256, 2) void attn_mma(const float* __restrict__ Q,
                                                   const float* __restrict__ K,
                                                   const float* __restrict__ Vt,
                                                   float* __restrict__ O,
                                                   int hOff) {
    extern __shared__ __align__(1024) float sma[];
    const uint32_t sb = smem_u32(sma);
    const int tid = threadIdx.x, lane = tid & 31, wid = tid >> 5;
    const int ms = wid >> 1, nh = wid & 1, g = lane >> 2, tig = lane & 3;
    const int qt = 31 - blockIdx.x;  // heavy tiles first
    const int h = blockIdx.y + hOff, b = blockIdx.z;
    const int q0 = qt * 64, bi = qt >> 2, sp = qt & 3;
    const size_t base = (size_t)b * Sc * Hc + (size_t)h * HDc;
    const float* Kb = K + base;
    const float* Qb = Q + base;
    const float* Vtb = Vt + ((size_t)(b * NHc + h) * HDc) * Sc;

    // load-slot geometry
    const int rowK = tid >> 5, colK = (tid & 31) * 4;    // K chunk: 64r x 128d
    const int rowV = tid >> 3, colV = (tid & 7) * 4;     // V chunk: 128d x 32k
    const uint32_t kRel = (uint32_t)(rowK * 132 + colK) * 4;
    const uint32_t vRel = (uint32_t)(rowV * 36 + colV) * 4;

    // prologue: Q tile + K block0 chunk0 into KV0 (one group)
#pragma unroll
    for (int i = 0; i < 8; ++i)
        cpa16(sb + (AQ + (rowK + 8 * i) * 132 + colK) * 4,
              Qb + (size_t)(q0 + rowK + 8 * i) * Hc + colK);
#pragma unroll
    for (int i = 0; i < 8; ++i)
        cpa16(sb + AKV0 * 4 + kRel + i * (8 * 132 * 4),
              Kb + (size_t)(rowK + 8 * i) * Hc + colK);
    cpa_commit();

    // fragment bases
    const int frow = (lane & 7) + ((lane >> 3) & 1) * 8;
    const uint32_t aQ = sb + ((AQ + (ms * 16 + frow) * 132 + ((lane >> 4) & 1) * 4) * 4);
    const int browk = (lane & 7) + ((lane >> 4) & 1) * 8;
    const uint32_t bcolk = ((lane >> 3) & 1) * 4;
    const uint32_t bK0rel = ((nh * 32 + browk) * 132 + bcolk) * 4;
    const uint32_t bK1rel = bK0rel + 16 * 132 * 4;
    // P fragment base, relative to KV buffer start
    const uint32_t aPcRel = (PSL + (ms * 16 + frow) * 36 + ((lane >> 4) & 1) * 4) * 4;
    uint32_t bVrel[4];
#pragma unroll
    for (int p = 0; p < 4; ++p)
        bVrel[p] = ((nh * 64 + p * 16 + browk) * 36 + bcolk) * 4;

    float o[8][4];
#pragma unroll
    for (int u = 0; u < 8; ++u)
#pragma unroll
        for (int e = 0; e < 4; ++e) o[u][e] = 0.f;

    int cur = 0;  // buffer holding the chunk about to be computed
    const int row0 = ms * 16 + g;
    const int qi0 = q0 + row0, qi1 = qi0 + 8;

    for (int j = 0; j <= bi; ++j) {
        const int nc = (j < bi) ? 4 : (sp + 1);
        const int kb = j * BSZ;
        float s[16][4];
#pragma unroll
        for (int t = 0; t < 16; ++t)
#pragma unroll
            for (int e = 0; e < 4; ++e) s[t][e] = 0.f;

        // ---- QK chunks: wait -> sync -> prefetch(other buf) -> compute ----
        for (int c = 0; c < nc; ++c) {
            cpa_wait0();
            __syncthreads();
            const uint32_t nb = sb + (cur ? AKV0 : AKV1) * 4;  // other buffer
            if (c + 1 < nc) {
                const int ka = kb + (c + 1) * 64;
#pragma unroll
                for (int i = 0; i < 8; ++i)
                    cpa16(nb + kRel + i * (8 * 132 * 4),
                          Kb + (size_t)(ka + rowK + 8 * i) * Hc + colK);
            } else {
                // first 32-key V chunk of this block
#pragma unroll
                for (int i = 0; i < 4; ++i)
                    cpa16(nb + vRel + i * (32 * 36 * 4),
                          Vtb + (size_t)(rowV + 32 * i) * Sc + kb + colV);
            }
            cpa_commit();

            const uint32_t bufb = sb + (cur ? AKV1 : AKV0) * 4;
#pragma unroll
            for (int ks = 0; ks < 16; ++ks) {
                uint32_t af[4];
                ldsm_x4(af, aQ + ks * 32);
                uint32_t bf[4];
                ldsm_x4(bf, bufb + bK0rel + ks * 32);
                mma_tf32(s[c * 4 + 0], af, bf[0], bf[1]);
                mma_tf32(s[c * 4 + 1], af, bf[2], bf[3]);
                ldsm_x4(bf, bufb + bK1rel + ks * 32);
                mma_tf32(s[c * 4 + 2], af, bf[0], bf[1]);
                mma_tf32(s[c * 4 + 3], af, bf[2], bf[3]);
            }
            cur ^= 1;
        }

        // ---- per-block softmax (unchanged numerics) ----
        const bool diag = (j == bi);
        const int ntile = nc * 4;
        float mx0 = -1e30f, mx1 = -1e30f;
        for (int t = 0; t < ntile; ++t) {
            if (diag) {
                int col = kb + 64 * (t >> 2) + nh * 32 + 8 * (t & 3) + 2 * tig;
                if (col > qi0) s[t][0] = -1e30f;
                if (col + 1 > qi0) s[t][1] = -1e30f;
                if (col > qi1) s[t][2] = -1e30f;
                if (col + 1 > qi1) s[t][3] = -1e30f;
            }
            mx0 = fmaxf(mx0, fmaxf(s[t][0], s[t][1]));
            mx1 = fmaxf(mx1, fmaxf(s[t][2], s[t][3]));
        }
        mx0 = fmaxf(mx0, __shfl_xor_sync(0xffffffffu, mx0, 1));
        mx0 = fmaxf(mx0, __shfl_xor_sync(0xffffffffu, mx0, 2));
        mx1 = fmaxf(mx1, __shfl_xor_sync(0xffffffffu, mx1, 1));
        mx1 = fmaxf(mx1, __shfl_xor_sync(0xffffffffu, mx1, 2));
        float l0 = 0.f, l1 = 0.f;
        for (int t = 0; t < ntile; ++t) {
            float p0 = (s[t][0] <= -1e29f) ? 0.f : __expf(SCALE * (s[t][0] - mx0));
            float p1 = (s[t][1] <= -1e29f) ? 0.f : __expf(SCALE * (s[t][1] - mx0));
            float p2 = (s[t][2] <= -1e29f) ? 0.f : __expf(SCALE * (s[t][2] - mx1));
            float p3 = (s[t][3] <= -1e29f) ? 0.f : __expf(SCALE * (s[t][3] - mx1));
            s[t][0] = p0; s[t][1] = p1; s[t][2] = p2; s[t][3] = p3;
            l0 += p0 + p1;
            l1 += p2 + p3;
        }
        l0 += __shfl_xor_sync(0xffffffffu, l0, 1);
        l0 += __shfl_xor_sync(0xffffffffu, l0, 2);
        l1 += __shfl_xor_sync(0xffffffffu, l1, 1);
        l1 += __shfl_xor_sync(0xffffffffu, l1, 2);
        if (tig == 0) {
            sma[ARED + row0 * 2 + nh] = mx0;
            sma[ARED + 128 + row0 * 2 + nh] = l0;
            sma[ARED + (row0 + 8) * 2 + nh] = mx1;
            sma[ARED + 128 + (row0 + 8) * 2 + nh] = l1;
        }
        __syncthreads();
        float f0, f1;
        {
            float mo0 = sma[ARED + row0 * 2 + (nh ^ 1)];
            float lo0 = sma[ARED + 128 + row0 * 2 + (nh ^ 1)];
            float mo1 = sma[ARED + (row0 + 8) * 2 + (nh ^ 1)];
            float lo1 = sma[ARED + 128 + (row0 + 8) * 2 + (nh ^ 1)];
            float M0 = fmaxf(mx0, mo0), M1 = fmaxf(mx1, mo1);
            float cc0 = __expf(SCALE * (mx0 - M0)), co0 = __expf(SCALE * (mo0 - M0));
            float cc1 = __expf(SCALE * (mx1 - M1)), co1 = __expf(SCALE * (mo1 - M1));
            f0 = cc0 / (l0 * cc0 + lo0 * co0 + 1e-30f);
            f1 = cc1 / (l1 * cc1 + lo1 * co1 + 1e-30f);
        }

        // ---- PV: 32-key chunks; P staged into the SAME buffer's slack ----
        const int nv = nc * 2;
        for (int c2 = 0; c2 < nv; ++c2) {
            const int kg = c2 >> 1, hh = c2 & 1;
            const uint32_t bufc = sb + (cur ? AKV1 : AKV0) * 4;  // compute buffer
            // stage P for this chunk into bufc slack (owning half only);
            // races only disjoint-address cp.async (V region) -> safe pre-wait
            if (nh == hh) {
#pragma unroll
                for (int tt = 0; tt < 4; ++tt) {
                    int t = kg * 4 + tt;
                    int col = 8 * tt + 2 * tig;
                    uint32_t a0 = bufc + (PSL + (ms * 16 + g) * 36 + col) * 4;
                    asm volatile("st.shared.v2.b32 [%0], {%1,%2};"
                                 :: "r"(a0), "r"(f2tf32(s[t][0] * f0)),
                                    "r"(f2tf32(s[t][1] * f0)) : "memory");
                    asm volatile("st.shared.v2.b32 [%0], {%1,%2};"
                                 :: "r"(a0 + 8 * 36 * 4), "r"(f2tf32(s[t][2] * f1)),
                                    "r"(f2tf32(s[t][3] * f1)) : "memory");
                }
            }
            cpa_wait0();
            __syncthreads();  // V chunk arrived + P visible to all warps
            const uint32_t nb = sb + (cur ? AKV0 : AKV1) * 4;
            if (c2 + 1 < nv) {
                const int ka = kb + (c2 + 1) * 32;
#pragma unroll
                for (int i = 0; i < 4; ++i)
                    cpa16(nb + vRel + i * (32 * 36 * 4),
                          Vtb + (size_t)(rowV + 32 * i) * Sc + ka + colV);
            } else if (j < bi) {
                const int ka = (j + 1) * BSZ;
#pragma unroll
                for (int i = 0; i < 8; ++i)
                    cpa16(nb + kRel + i * (8 * 132 * 4),
                          Kb + (size_t)(ka + rowK + 8 * i) * Hc + colK);
            }
            cpa_commit();

#pragma unroll
            for (int ks = 0; ks < 4; ++ks) {
                uint32_t af[4];
                ldsm_x4(af, bufc + aPcRel + ks * 32);
#pragma unroll
                for (int p = 0; p < 4; ++p) {
                    uint32_t bf[4];
                    ldsm_x4(bf, bufc + bVrel[p] + ks * 32);
                    mma_tf32(o[2 * p], af, bf[0], bf[1]);
                    mma_tf32(o[2 * p + 1], af, bf[2], bf[3]);
                }
            }
            cur ^= 1;
        }
    }

    // epilogue: tf32-rounded output (feeds raw-bit Wo GEMM)
    const float invn = 1.f / ((float)(bi + 1) + 1e-6f);
#pragma unroll
    for (int u = 0; u < 8; ++u) {
        int d = nh * 64 + 16 * (u >> 1) + 8 * (u & 1) + 2 * tig;
        *(float2*)(O + base + (size_t)qi0 * Hc + d) =
            make_float2(rnd_tf32(o[u][0] * invn), rnd_tf32(o[u][1] * invn));
        *(float2*)(O + base + (size_t)qi1 * Hc + d) =
            make_float2(rnd_tf32(o[u][2] * invn), rnd_tf32(o[u][3] * invn));
    }
}

// ---------------------------------------------------------------------------
extern "C" void kernel_launch(void* const* d_in, const int* in_sizes, int n_in,
                              void* d_out, int out_size) {
    const float* hs = (const float*)d_in[0];
    const float* Wq = (const float*)d_in[1];
    const float* Wk = (const float*)d_in[2];
    const float* Wv = (const float*)d_in[3];
    const float* Wo = (const float*)d_in[4];
    float* out = (float*)d_out;

    float *qp, *kp, *vtp, *aop, *hsr, *wr;
    cudaGetSymbolAddress((void**)&qp, g_q);
    cudaGetSymbolAddress((void**)&kp, g_k);
    cudaGetSymbolAddress((void**)&vtp, g_vt);
    cudaGetSymbolAddress((void**)&aop, g_ao);
    cudaGetSymbolAddress((void**)&hsr, g_hsr);
    cudaGetSymbolAddress((void**)&wr, g_wr);
    float* wor = wr + 3 * (size_t)Hc * Hc;

    static int init_done = 0;
    static cudaStream_t s2;
    static cudaEvent_t evR, ev1;
    if (!init_done) {
        cudaFuncSetAttribute(gemm_qkv, cudaFuncAttributeMaxDynamicSharedMemorySize,
                             GEMM_SMEM);
        cudaFuncSetAttribute(gemm_wo, cudaFuncAttributeMaxDynamicSharedMemorySize,
                             GEMM_SMEM);
        cudaFuncSetAttribute(attn_mma, cudaFuncAttributeMaxDynamicSharedMemorySize,
                             ATTN_SMEM);
        cudaStreamCreateWithFlags(&s2, cudaStreamNonBlocking);
        cudaEventCreateWithFlags(&evR, cudaEventDisableTiming);
        cudaEventCreateWithFlags(&ev1, cudaEventDisableTiming);
        init_done = 1;
    }

    const int nTot4 = (Bc * Sc * Hc + 4 * Hc * Hc) / 4;  // 6M
    round_all<<<nTot4 / 1024, 256>>>(hs, Wq, Wk, Wv, Wo, hsr, wr);
    cudaEventRecord(evR, 0);
    cudaStreamWaitEvent(s2, evR, 0);

    dim3 gqh(24, Mc / 128);  // half of QKV: 768 CTAs
    dim3 gah(32, NHc / 2, Bc);
    // half B on second stream (heads 8-15)
    gemm_qkv<<<gqh, 256, GEMM_SMEM, s2>>>(hsr, wr, qp, kp, vtp, 8);
    attn_mma<<<gah, 256, ATTN_SMEM, s2>>>(qp, kp, vtp, aop, 8);
    cudaEventRecord(ev1, s2);
    // half A on default stream (heads 0-7)
    gemm_qkv<<<gqh, 256, GEMM_SMEM>>>(hsr, wr, qp, kp, vtp, 0);
    attn_mma<<<gah, 256, ATTN_SMEM>>>(qp, kp, vtp, aop, 0);
    cudaStreamWaitEvent(0, ev1, 0);

    dim3 gw(Hc / 128, Mc / 128);  // (16, 32)
    gemm_wo<<<gw, 256, GEMM_SMEM>>>(aop, wor, out);
}